// round 1
// baseline (speedup 1.0000x reference)
#include <cuda_runtime.h>
#include <math.h>

// Problem constants (B=1)
#define Lc     2048
#define Hc     16
#define Dc     64
#define Mc     24
#define Wc     128
#define CHUNK  128
#define NC     16           // Lc / CHUNK
#define SCALEc 0.125f
#define EPSc   1e-4f
#define DN     0.35355339059327373f   // sqrt(0.125)
#define LN24   3.1780538303479458f    // log(24) = 2 * half_log_m

// ---------------- scratch (device globals; no allocations) ----------------
__device__ float g_kprime[Hc * Lc * Mc];          // k' features
__device__ float g_chunkmax[Hc * NC];             // per-chunk max of k x_dash
__device__ float g_kstab[Hc];                     // per-head key stabilizer
__device__ float g_ksum [Hc * NC * Mc];           // per-chunk sum of k'
__device__ float g_kvsum[Hc * NC * Mc * Dc];      // per-chunk sum of k' (x) v
__device__ float g_kbase [Hc * NC * Mc];          // exclusive prefixes
__device__ float g_kvbase[Hc * NC * Mc * Dc];

// ---------------- kernel 1: per-(head,chunk) max of key x_dash ------------
__global__ void __launch_bounds__(128) k1_kmax(const float* __restrict__ qkv,
                                               const float* __restrict__ proj)
{
    __shared__ float proj_s[Mc * Dc];
    __shared__ float red[128];
    const int c = blockIdx.x, h = blockIdx.y, t = threadIdx.x;

    for (int f = t; f < Mc * Dc / 4; f += 128)
        ((float4*)proj_s)[f] = ((const float4*)proj)[f];
    __syncthreads();

    const int l = c * CHUNK + t;
    float k[Dc];
    const float4* kr = (const float4*)(qkv + ((size_t)(l * 3 + 1) * Hc + h) * Dc);
#pragma unroll
    for (int dv = 0; dv < 16; dv++) {
        float4 x = kr[dv];
        k[4*dv] = x.x; k[4*dv+1] = x.y; k[4*dv+2] = x.z; k[4*dv+3] = x.w;
    }
    float mx = -3.4e38f;
#pragma unroll
    for (int m = 0; m < Mc; m++) {
        const float* pr = proj_s + m * Dc;
        float d0 = 0.f, d1 = 0.f, d2 = 0.f, d3 = 0.f;
#pragma unroll
        for (int d = 0; d < Dc; d += 4) {
            d0 = fmaf(pr[d  ], k[d  ], d0);
            d1 = fmaf(pr[d+1], k[d+1], d1);
            d2 = fmaf(pr[d+2], k[d+2], d2);
            d3 = fmaf(pr[d+3], k[d+3], d3);
        }
        mx = fmaxf(mx, ((d0 + d1) + (d2 + d3)) * DN);
    }
    red[t] = mx;
    __syncthreads();
    for (int s = 64; s > 0; s >>= 1) {
        if (t < s) red[t] = fmaxf(red[t], red[t + s]);
        __syncthreads();
    }
    if (t == 0) g_chunkmax[h * NC + c] = red[0];
}

// ---------------- kernel 2: k' + per-chunk sums ----------------------------
__global__ void __launch_bounds__(128) k2_kprime(const float* __restrict__ qkv,
                                                 const float* __restrict__ proj)
{
    __shared__ float buf[CHUNK * Dc];   // holds proj first, then v tile
    __shared__ float kp_s[CHUNK * 25];  // padded stride 25
    const int c = blockIdx.x, h = blockIdx.y, t = threadIdx.x;

    float kstab = -3.4e38f;
#pragma unroll
    for (int cc = 0; cc < NC; cc++) kstab = fmaxf(kstab, g_chunkmax[h * NC + cc]);
    if (c == 0 && t == 0) g_kstab[h] = kstab;

    for (int f = t; f < Mc * Dc / 4; f += 128)
        ((float4*)buf)[f] = ((const float4*)proj)[f];
    __syncthreads();

    const int l = c * CHUNK + t;
    float k[Dc];
    const float4* kr = (const float4*)(qkv + ((size_t)(l * 3 + 1) * Hc + h) * Dc);
#pragma unroll
    for (int dv = 0; dv < 16; dv++) {
        float4 x = kr[dv];
        k[4*dv] = x.x; k[4*dv+1] = x.y; k[4*dv+2] = x.z; k[4*dv+3] = x.w;
    }
    float xn = 0.f;
#pragma unroll
    for (int d = 0; d < Dc; d++) xn = fmaf(k[d], k[d], xn);
    xn *= 0.0625f;   // 0.5 * dn^2 * sum(k^2)

    float xd[Mc];
#pragma unroll
    for (int m = 0; m < Mc; m++) {
        const float* pr = buf + m * Dc;
        float d0 = 0.f, d1 = 0.f, d2 = 0.f, d3 = 0.f;
#pragma unroll
        for (int d = 0; d < Dc; d += 4) {
            d0 = fmaf(pr[d  ], k[d  ], d0);
            d1 = fmaf(pr[d+1], k[d+1], d1);
            d2 = fmaf(pr[d+2], k[d+2], d2);
            d3 = fmaf(pr[d+3], k[d+3], d3);
        }
        xd[m] = ((d0 + d1) + (d2 + d3)) * DN;
    }
    __syncthreads();   // done with proj; reuse buf for v

    const float4* vr = (const float4*)(qkv + ((size_t)(l * 3 + 2) * Hc + h) * Dc);
    float4* vb = (float4*)(buf + t * Dc);
#pragma unroll
    for (int dv = 0; dv < 16; dv++) vb[dv] = vr[dv];

    float* kpo = g_kprime + ((size_t)h * Lc + l) * Mc;
#pragma unroll
    for (int m = 0; m < Mc; m++) {
        float val = __expf(xd[m] - xn - kstab) + EPSc;
        kp_s[t * 25 + m] = val;
        kpo[m] = val;
    }
    __syncthreads();

    float* kvo = g_kvsum + ((size_t)(h * NC + c)) * Mc * Dc;
#pragma unroll
    for (int r = 0; r < 12; r++) {
        int o = t + 128 * r;
        int m = o >> 6, d = o & 63;
        float a0 = 0.f, a1 = 0.f;
        for (int row = 0; row < CHUNK; row += 2) {
            a0 = fmaf(kp_s[row * 25 + m],       buf[row * Dc + d],       a0);
            a1 = fmaf(kp_s[(row + 1) * 25 + m], buf[(row + 1) * Dc + d], a1);
        }
        kvo[o] = a0 + a1;
    }
    if (t < Mc) {
        float a = 0.f;
        for (int row = 0; row < CHUNK; row++) a += kp_s[row * 25 + t];
        g_ksum[(h * NC + c) * Mc + t] = a;
    }
}

// ---------------- kernel 3: exclusive scan across chunks -------------------
__global__ void __launch_bounds__(256) k3_scan()
{
    const int h = blockIdx.x, t = threadIdx.x;
    for (int e = t; e < Mc * Dc; e += 256) {
        float run = 0.f;
#pragma unroll
        for (int c = 0; c < NC; c++) {
            size_t idx = ((size_t)(h * NC + c)) * Mc * Dc + e;
            g_kvbase[idx] = run;
            run += g_kvsum[idx];
        }
    }
    if (t < Mc) {
        float run = 0.f;
#pragma unroll
        for (int c = 0; c < NC; c++) {
            int idx = (h * NC + c) * Mc + t;
            g_kbase[idx] = run;
            run += g_ksum[idx];
        }
    }
}

// ---------------- kernel 4: main fused attention ---------------------------
// smem layout (floats): k_s[256*64] v_s[256*64] kp_s[256*24] kvb_s[24*64]
//                       proj_s[24*64] kb_s[24]
#define SM4_FLOATS (256*64 + 256*64 + 256*24 + 24*64 + 24*64 + 32)

__global__ void __launch_bounds__(128, 1) k4_main(const float* __restrict__ qkv,
                                                  const float* __restrict__ proj,
                                                  float* __restrict__ out)
{
    extern __shared__ float sm[];
    float* k_s    = sm;
    float* v_s    = k_s  + 256 * Dc;
    float* kp_s   = v_s  + 256 * Dc;
    float* kvb_s  = kp_s + 256 * Mc;
    float* proj_s = kvb_s + Mc * Dc;
    float* kb_s   = proj_s + Mc * Dc;

    const int c = blockIdx.x, h = blockIdx.y, t = threadIdx.x;
    const int tilebase = (c > 0) ? (c - 1) * CHUNK : 0;
    const int nkeys    = (c > 0) ? 256 : 128;

    // cooperative tile loads (coalesced float4)
    for (int f = t; f < nkeys * 16; f += 128) {
        int r = f >> 4, dv = f & 15;
        int l = tilebase + r;
        ((float4*)k_s)[r * 16 + dv] = ((const float4*)(qkv + ((size_t)(l * 3 + 1) * Hc + h) * Dc))[dv];
        ((float4*)v_s)[r * 16 + dv] = ((const float4*)(qkv + ((size_t)(l * 3 + 2) * Hc + h) * Dc))[dv];
    }
    {
        const float4* kpsrc = (const float4*)(g_kprime + ((size_t)h * Lc + tilebase) * Mc);
        for (int f = t; f < nkeys * 6; f += 128) ((float4*)kp_s)[f] = kpsrc[f];
        const float4* kvbsrc = (const float4*)(g_kvbase + ((size_t)(h * NC + c)) * Mc * Dc);
        for (int f = t; f < Mc * Dc / 4; f += 128) {
            ((float4*)kvb_s)[f]  = kvbsrc[f];
            ((float4*)proj_s)[f] = ((const float4*)proj)[f];
        }
        if (t < Mc) kb_s[t] = g_kbase[(h * NC + c) * Mc + t];
    }
    __syncthreads();

    const float kstab = g_kstab[h];
    const int i = c * CHUNK + t;

    // ---- query features ----
    float q[Dc];
    {
        const float4* qr = (const float4*)(qkv + ((size_t)(i * 3 + 0) * Hc + h) * Dc);
#pragma unroll
        for (int dv = 0; dv < 16; dv++) {
            float4 x = qr[dv];
            q[4*dv] = x.x; q[4*dv+1] = x.y; q[4*dv+2] = x.z; q[4*dv+3] = x.w;
        }
    }
    float xn = 0.f;
#pragma unroll
    for (int d = 0; d < Dc; d++) xn = fmaf(q[d], q[d], xn);
    xn *= 0.0625f;

    float qp[Mc];
    float qstab = -3.4e38f;
#pragma unroll
    for (int m = 0; m < Mc; m++) {
        const float* pr = proj_s + m * Dc;
        float d0 = 0.f, d1 = 0.f, d2 = 0.f, d3 = 0.f;
#pragma unroll
        for (int d = 0; d < Dc; d += 4) {
            d0 = fmaf(pr[d  ], q[d  ], d0);
            d1 = fmaf(pr[d+1], q[d+1], d1);
            d2 = fmaf(pr[d+2], q[d+2], d2);
            d3 = fmaf(pr[d+3], q[d+3], d3);
        }
        float xd = ((d0 + d1) + (d2 + d3)) * DN;
        qp[m] = xd;
        qstab = fmaxf(qstab, xd);
    }
#pragma unroll
    for (int m = 0; m < Mc; m++) qp[m] = __expf(qp[m] - qstab) + EPSc;

    const float gs = qstab - xn + kstab - LN24;   // global_scale
    float kbdot = 0.f;
#pragma unroll
    for (int m = 0; m < Mc; m++) kbdot = fmaf(qp[m], kb_s[m], kbdot);

    // warp-uniform band bounds
    const int warp = t >> 5;
    const int qb = c * CHUNK + warp * 32;
    int jlo = qb - Wc - tilebase; if (jlo < 0) jlo = 0;
    const int jhi = qb + 31 - tilebase;
    const int cstart = c * CHUNK;

    // ---- pass 1: softmax stats + weighted feature-score sum ----
    float mx = -1e30f, Z = 0.f, Asc = 0.f;
    for (int j = jlo; j <= jhi; j++) {
        const int jg = tilebase + j;
        const bool act = (jg <= i) && (jg >= i - Wc);

        const float4* kr4 = (const float4*)(k_s + j * Dc);
        float s0 = 0.f, s1 = 0.f, s2 = 0.f, s3 = 0.f;
#pragma unroll
        for (int dv = 0; dv < 16; dv++) {
            float4 kk = kr4[dv];
            s0 = fmaf(q[4*dv  ], kk.x, s0);
            s1 = fmaf(q[4*dv+1], kk.y, s1);
            s2 = fmaf(q[4*dv+2], kk.z, s2);
            s3 = fmaf(q[4*dv+3], kk.w, s3);
        }
        float s = ((s0 + s1) + (s2 + s3)) * SCALEc;

        const float4* kp4 = (const float4*)(kp_s + j * Mc);
        float g0 = 0.f, g1 = 0.f, g2 = 0.f, g3 = 0.f;
#pragma unroll
        for (int mv = 0; mv < 6; mv++) {
            float4 kk = kp4[mv];
            g0 = fmaf(qp[4*mv  ], kk.x, g0);
            g1 = fmaf(qp[4*mv+1], kk.y, g1);
            g2 = fmaf(qp[4*mv+2], kk.z, g2);
            g3 = fmaf(qp[4*mv+3], kk.w, g3);
        }
        float g = (g0 + g1) + (g2 + g3);
        float w = (jg >= cstart) ? 0.875f : -0.125f;

        if (act) {
            Asc += w * g;
            float nm = fmaxf(mx, s);
            Z = Z * __expf(mx - nm) + __expf(s - nm);
            mx = nm;
        }
    }

    const float lse = mx + __logf(Z);
    const float gln = __logf(fmaxf(kbdot + Asc, 1e-24f)) + gs;
    float a = fmaxf(lse, gln), b = fminf(lse, gln);
    const float lnorm = a + log1pf(__expf(b - a));
    const float gps = __expf(gs - lnorm);

    // ---- pass 2: accumulate output ----
    float o[Dc];
#pragma unroll
    for (int d = 0; d < Dc; d++) o[d] = 0.f;

    for (int j = jlo; j <= jhi; j++) {
        const int jg = tilebase + j;
        const bool act = (jg <= i) && (jg >= i - Wc);

        const float4* kr4 = (const float4*)(k_s + j * Dc);
        float s0 = 0.f, s1 = 0.f, s2 = 0.f, s3 = 0.f;
#pragma unroll
        for (int dv = 0; dv < 16; dv++) {
            float4 kk = kr4[dv];
            s0 = fmaf(q[4*dv  ], kk.x, s0);
            s1 = fmaf(q[4*dv+1], kk.y, s1);
            s2 = fmaf(q[4*dv+2], kk.z, s2);
            s3 = fmaf(q[4*dv+3], kk.w, s3);
        }
        float s = ((s0 + s1) + (s2 + s3)) * SCALEc;

        const float4* kp4 = (const float4*)(kp_s + j * Mc);
        float g0 = 0.f, g1 = 0.f, g2 = 0.f, g3 = 0.f;
#pragma unroll
        for (int mv = 0; mv < 6; mv++) {
            float4 kk = kp4[mv];
            g0 = fmaf(qp[4*mv  ], kk.x, g0);
            g1 = fmaf(qp[4*mv+1], kk.y, g1);
            g2 = fmaf(qp[4*mv+2], kk.z, g2);
            g3 = fmaf(qp[4*mv+3], kk.w, g3);
        }
        float g = (g0 + g1) + (g2 + g3);
        float w = (jg >= cstart) ? 0.875f : -0.125f;

        float coef = act ? (__expf(s - lse) + gps * w * g) : 0.f;

        const float4* vr4 = (const float4*)(v_s + j * Dc);
#pragma unroll
        for (int dv = 0; dv < 16; dv++) {
            float4 vv = vr4[dv];
            o[4*dv  ] = fmaf(coef, vv.x, o[4*dv  ]);
            o[4*dv+1] = fmaf(coef, vv.y, o[4*dv+1]);
            o[4*dv+2] = fmaf(coef, vv.z, o[4*dv+2]);
            o[4*dv+3] = fmaf(coef, vv.w, o[4*dv+3]);
        }
    }

    // add gps * (q' . KVbase)
#pragma unroll
    for (int m = 0; m < Mc; m++) {
        float cm = gps * qp[m];
        const float4* kb4 = (const float4*)(kvb_s + m * Dc);
#pragma unroll
        for (int dv = 0; dv < 16; dv++) {
            float4 x = kb4[dv];
            o[4*dv  ] = fmaf(cm, x.x, o[4*dv  ]);
            o[4*dv+1] = fmaf(cm, x.y, o[4*dv+1]);
            o[4*dv+2] = fmaf(cm, x.z, o[4*dv+2]);
            o[4*dv+3] = fmaf(cm, x.w, o[4*dv+3]);
        }
    }

    float4* orow = (float4*)(out + ((size_t)i * Hc + h) * Dc);
#pragma unroll
    for (int dv = 0; dv < 16; dv++)
        orow[dv] = make_float4(o[4*dv], o[4*dv+1], o[4*dv+2], o[4*dv+3]);
}

// ---------------- launch ----------------------------------------------------
extern "C" void kernel_launch(void* const* d_in, const int* in_sizes, int n_in,
                              void* d_out, int out_size)
{
    (void)out_size;
    const float* qkv  = (const float*)d_in[0];
    const float* proj = (const float*)d_in[1];
    if (n_in >= 2 && in_sizes[0] < in_sizes[1]) {  // defensive order check
        const float* tmp = qkv; qkv = proj; proj = tmp;
    }
    float* out = (float*)d_out;

    cudaFuncSetAttribute(k4_main, cudaFuncAttributeMaxDynamicSharedMemorySize,
                         SM4_FLOATS * (int)sizeof(float));

    dim3 grid(NC, Hc);
    k1_kmax  <<<grid, 128>>>(qkv, proj);
    k2_kprime<<<grid, 128>>>(qkv, proj);
    k3_scan  <<<Hc, 256>>>();
    k4_main  <<<grid, 128, SM4_FLOATS * (int)sizeof(float)>>>(qkv, proj, out);
}

// round 2
// speedup vs baseline: 1.0608x; 1.0608x over previous
#include <cuda_runtime.h>
#include <math.h>

// Problem constants (B=1)
#define Lc     2048
#define Hc     16
#define Dc     64
#define Mc     24
#define Wc     128
#define CHUNK  128
#define NC     16           // Lc / CHUNK
#define SCALEc 0.125f
#define EPSc   1e-4f
#define DN     0.35355339059327373f   // sqrt(0.125)
#define LN24   3.1780538303479458f    // log(24)

// ---------------- scratch (device globals; no allocations) ----------------
__device__ float g_xdash[Hc * NC * Mc * CHUNK];   // key x_dash, layout [hc][m][t]
__device__ float g_xn[Hc * NC * CHUNK];           // key x_norm
__device__ float g_kprime[Hc * Lc * Mc];          // k' features [h][l][m]
__device__ float g_chunkmax[Hc * NC];             // per-chunk max of key x_dash
__device__ float g_kstab[Hc];                     // per-head key stabilizer
__device__ float g_ksum [Hc * NC * Mc];           // per-chunk sum of k'
__device__ float g_kvsum[Hc * NC * Mc * Dc];      // per-chunk sum of k' (x) v
__device__ float g_kbase [Hc * NC * Mc];          // exclusive prefixes
__device__ float g_kvbase[Hc * NC * Mc * Dc];

// ---------------- kernel 1: key features (x_dash, x_norm) + chunk max ------
__global__ void __launch_bounds__(128) k1_feat(const float* __restrict__ qkv,
                                               const float* __restrict__ proj)
{
    __shared__ float proj_s[Mc * Dc];
    __shared__ float red[128];
    const int c = blockIdx.x, h = blockIdx.y, t = threadIdx.x;
    const int hc = h * NC + c;

    for (int f = t; f < Mc * Dc / 4; f += 128)
        ((float4*)proj_s)[f] = ((const float4*)proj)[f];
    __syncthreads();

    const int l = c * CHUNK + t;
    float k[Dc];
    const float4* kr = (const float4*)(qkv + ((size_t)(l * 3 + 1) * Hc + h) * Dc);
#pragma unroll
    for (int dv = 0; dv < 16; dv++) {
        float4 x = kr[dv];
        k[4*dv] = x.x; k[4*dv+1] = x.y; k[4*dv+2] = x.z; k[4*dv+3] = x.w;
    }
    float xn = 0.f;
#pragma unroll
    for (int d = 0; d < Dc; d++) xn = fmaf(k[d], k[d], xn);
    g_xn[hc * CHUNK + t] = xn * 0.0625f;

    float mx = -3.4e38f;
#pragma unroll
    for (int m = 0; m < Mc; m++) {
        const float* pr = proj_s + m * Dc;
        float d0 = 0.f, d1 = 0.f, d2 = 0.f, d3 = 0.f;
#pragma unroll
        for (int d = 0; d < Dc; d += 4) {
            d0 = fmaf(pr[d  ], k[d  ], d0);
            d1 = fmaf(pr[d+1], k[d+1], d1);
            d2 = fmaf(pr[d+2], k[d+2], d2);
            d3 = fmaf(pr[d+3], k[d+3], d3);
        }
        float xd = ((d0 + d1) + (d2 + d3)) * DN;
        g_xdash[(hc * Mc + m) * CHUNK + t] = xd;
        mx = fmaxf(mx, xd);
    }
    red[t] = mx;
    __syncthreads();
    for (int s = 64; s > 0; s >>= 1) {
        if (t < s) red[t] = fmaxf(red[t], red[t + s]);
        __syncthreads();
    }
    if (t == 0) g_chunkmax[hc] = red[0];
}

// ---------------- kernel 2: k' + per-chunk sums -----------------------------
__global__ void __launch_bounds__(128) k2_kprime(const float* __restrict__ qkv)
{
    __shared__ float vbuf[CHUNK * Dc];   // v tile
    __shared__ float kp_s[CHUNK * 25];   // padded stride 25
    const int c = blockIdx.x, h = blockIdx.y, t = threadIdx.x;
    const int hc = h * NC + c;

    float kstab = -3.4e38f;
#pragma unroll
    for (int cc = 0; cc < NC; cc++) kstab = fmaxf(kstab, g_chunkmax[h * NC + cc]);
    if (c == 0 && t == 0) g_kstab[h] = kstab;

    // coalesced v tile load: 16 consecutive lanes fetch one row's 16 float4s
    const int tilebase = c * CHUNK;
    for (int f = t; f < CHUNK * 16; f += 128) {
        int r = f >> 4, dv = f & 15;
        ((float4*)vbuf)[f] =
            ((const float4*)(qkv + ((size_t)((tilebase + r) * 3 + 2) * Hc + h) * Dc))[dv];
    }

    const float xn = g_xn[hc * CHUNK + t];
    const int l = tilebase + t;
    float* kpo = g_kprime + ((size_t)h * Lc + l) * Mc;
#pragma unroll
    for (int m = 0; m < Mc; m++) {
        float xd = g_xdash[(hc * Mc + m) * CHUNK + t];
        float val = __expf(xd - xn - kstab) + EPSc;
        kp_s[t * 25 + m] = val;
        kpo[m] = val;
    }
    __syncthreads();

    // kvsum: 384 float4 outputs (24 m x 16 d4), 3 per thread
    float4* kvo4 = (float4*)(g_kvsum + (size_t)hc * Mc * Dc);
    const float4* vb4 = (const float4*)vbuf;
#pragma unroll
    for (int grp = 0; grp < 3; grp++) {
        int o = t + 128 * grp;
        int m = o >> 4, d4 = o & 15;
        float4 a = make_float4(0.f, 0.f, 0.f, 0.f);
        for (int row = 0; row < CHUNK; row++) {
            float kp = kp_s[row * 25 + m];
            float4 v = vb4[row * 16 + d4];
            a.x = fmaf(kp, v.x, a.x);
            a.y = fmaf(kp, v.y, a.y);
            a.z = fmaf(kp, v.z, a.z);
            a.w = fmaf(kp, v.w, a.w);
        }
        kvo4[o] = a;
    }
    if (t < Mc) {
        float a = 0.f;
        for (int row = 0; row < CHUNK; row++) a += kp_s[row * 25 + t];
        g_ksum[hc * Mc + t] = a;
    }
}

// ---------------- kernel 3: exclusive scan across chunks -------------------
__global__ void __launch_bounds__(256) k3_scan()
{
    const int h = blockIdx.x, t = threadIdx.x;
    for (int e = t; e < Mc * Dc; e += 256) {
        float run = 0.f;
#pragma unroll
        for (int c = 0; c < NC; c++) {
            size_t idx = ((size_t)(h * NC + c)) * Mc * Dc + e;
            g_kvbase[idx] = run;
            run += g_kvsum[idx];
        }
    }
    if (t < Mc) {
        float run = 0.f;
#pragma unroll
        for (int c = 0; c < NC; c++) {
            int idx = (h * NC + c) * Mc + t;
            g_kbase[idx] = run;
            run += g_ksum[idx];
        }
    }
}

// ---------------- kernel 4: main fused attention ----------------------------
// smem (floats): k_s[256*64] kp_s[256*24] kvb_s[24*64] proj_s[24*64] kb_s[32]
// = 25632 floats = 100.1 KB  -> 2 CTAs/SM
#define SM4_FLOATS (256*64 + 256*24 + 24*64 + 24*64 + 32)

__global__ void __launch_bounds__(128, 2) k4_main(const float* __restrict__ qkv,
                                                  const float* __restrict__ proj,
                                                  float* __restrict__ out)
{
    extern __shared__ float sm[];
    float* k_s    = sm;
    float* kp_s   = k_s  + 256 * Dc;
    float* kvb_s  = kp_s + 256 * Mc;
    float* proj_s = kvb_s + Mc * Dc;
    float* kb_s   = proj_s + Mc * Dc;

    const int c = blockIdx.x, h = blockIdx.y, t = threadIdx.x;
    const int tilebase = (c > 0) ? (c - 1) * CHUNK : 0;
    const int nkeys    = (c > 0) ? 256 : 128;

    // cooperative tile loads (coalesced float4)
    for (int f = t; f < nkeys * 16; f += 128) {
        int r = f >> 4, dv = f & 15;
        int l = tilebase + r;
        ((float4*)k_s)[r * 16 + dv] =
            ((const float4*)(qkv + ((size_t)(l * 3 + 1) * Hc + h) * Dc))[dv];
    }
    {
        const float4* kpsrc = (const float4*)(g_kprime + ((size_t)h * Lc + tilebase) * Mc);
        for (int f = t; f < nkeys * 6; f += 128) ((float4*)kp_s)[f] = kpsrc[f];
        const float4* kvbsrc = (const float4*)(g_kvbase + ((size_t)(h * NC + c)) * Mc * Dc);
        for (int f = t; f < Mc * Dc / 4; f += 128) {
            ((float4*)kvb_s)[f]  = kvbsrc[f];
            ((float4*)proj_s)[f] = ((const float4*)proj)[f];
        }
        if (t < Mc) kb_s[t] = g_kbase[(h * NC + c) * Mc + t];
    }
    __syncthreads();

    const float kstab = g_kstab[h];
    const int i = c * CHUNK + t;

    // ---- query features ----
    float q[Dc];
    {
        const float4* qr = (const float4*)(qkv + ((size_t)(i * 3 + 0) * Hc + h) * Dc);
#pragma unroll
        for (int dv = 0; dv < 16; dv++) {
            float4 x = qr[dv];
            q[4*dv] = x.x; q[4*dv+1] = x.y; q[4*dv+2] = x.z; q[4*dv+3] = x.w;
        }
    }
    float xn = 0.f;
#pragma unroll
    for (int d = 0; d < Dc; d++) xn = fmaf(q[d], q[d], xn);
    xn *= 0.0625f;

    float qp[Mc];
    float qstab = -3.4e38f;
#pragma unroll
    for (int m = 0; m < Mc; m++) {
        const float* pr = proj_s + m * Dc;
        float d0 = 0.f, d1 = 0.f, d2 = 0.f, d3 = 0.f;
#pragma unroll
        for (int d = 0; d < Dc; d += 4) {
            d0 = fmaf(pr[d  ], q[d  ], d0);
            d1 = fmaf(pr[d+1], q[d+1], d1);
            d2 = fmaf(pr[d+2], q[d+2], d2);
            d3 = fmaf(pr[d+3], q[d+3], d3);
        }
        float xd = ((d0 + d1) + (d2 + d3)) * DN;
        qp[m] = xd;
        qstab = fmaxf(qstab, xd);
    }
#pragma unroll
    for (int m = 0; m < Mc; m++) qp[m] = __expf(qp[m] - qstab) + EPSc;

    const float gs = qstab - xn + kstab - LN24;   // global_scale
    float kbdot = 0.f;
#pragma unroll
    for (int m = 0; m < Mc; m++) kbdot = fmaf(qp[m], kb_s[m], kbdot);

    // warp-uniform band bounds
    const int warp = t >> 5;
    const int qb = c * CHUNK + warp * 32;
    int jlo = qb - Wc - tilebase; if (jlo < 0) jlo = 0;
    const int jhi = qb + 31 - tilebase;
    const int cstart = c * CHUNK;

    // ---- pass 1: softmax stats + weighted feature-score sum ----
    float mx = -1e30f, Z = 0.f, Asc = 0.f;
    for (int j = jlo; j <= jhi; j++) {
        const int jg = tilebase + j;
        const bool act = (jg <= i) && (jg >= i - Wc);

        const float4* kr4 = (const float4*)(k_s + j * Dc);
        float s0 = 0.f, s1 = 0.f, s2 = 0.f, s3 = 0.f;
#pragma unroll
        for (int dv = 0; dv < 16; dv++) {
            float4 kk = kr4[dv];
            s0 = fmaf(q[4*dv  ], kk.x, s0);
            s1 = fmaf(q[4*dv+1], kk.y, s1);
            s2 = fmaf(q[4*dv+2], kk.z, s2);
            s3 = fmaf(q[4*dv+3], kk.w, s3);
        }
        float s = ((s0 + s1) + (s2 + s3)) * SCALEc;

        const float4* kp4 = (const float4*)(kp_s + j * Mc);
        float g0 = 0.f, g1 = 0.f, g2 = 0.f, g3 = 0.f;
#pragma unroll
        for (int mv = 0; mv < 6; mv++) {
            float4 kk = kp4[mv];
            g0 = fmaf(qp[4*mv  ], kk.x, g0);
            g1 = fmaf(qp[4*mv+1], kk.y, g1);
            g2 = fmaf(qp[4*mv+2], kk.z, g2);
            g3 = fmaf(qp[4*mv+3], kk.w, g3);
        }
        float g = (g0 + g1) + (g2 + g3);
        float w = (jg >= cstart) ? 0.875f : -0.125f;

        if (act) {
            Asc += w * g;
            float nm = fmaxf(mx, s);
            Z = Z * __expf(mx - nm) + __expf(s - nm);
            mx = nm;
        }
    }

    const float lse = mx + __logf(Z);
    const float gln = __logf(fmaxf(kbdot + Asc, 1e-24f)) + gs;
    float a = fmaxf(lse, gln), b = fminf(lse, gln);
    const float lnorm = a + log1pf(__expf(b - a));
    const float gps = __expf(gs - lnorm);

    // ---- pass 2: accumulate output (V streamed from L2 via LDG) ----
    float o[Dc];
#pragma unroll
    for (int d = 0; d < Dc; d++) o[d] = 0.f;

    const float4* vr4 = (const float4*)(qkv + ((size_t)((tilebase + jlo) * 3 + 2) * Hc + h) * Dc);
    const size_t vstep = 3 * Hc * Dc / 4;  // float4 stride per key

    for (int j = jlo; j <= jhi; j++, vr4 += vstep) {
        const int jg = tilebase + j;
        const bool act = (jg <= i) && (jg >= i - Wc);

        const float4* kr4 = (const float4*)(k_s + j * Dc);
        float s0 = 0.f, s1 = 0.f, s2 = 0.f, s3 = 0.f;
#pragma unroll
        for (int dv = 0; dv < 16; dv++) {
            float4 kk = kr4[dv];
            s0 = fmaf(q[4*dv  ], kk.x, s0);
            s1 = fmaf(q[4*dv+1], kk.y, s1);
            s2 = fmaf(q[4*dv+2], kk.z, s2);
            s3 = fmaf(q[4*dv+3], kk.w, s3);
        }
        float s = ((s0 + s1) + (s2 + s3)) * SCALEc;

        const float4* kp4 = (const float4*)(kp_s + j * Mc);
        float g0 = 0.f, g1 = 0.f, g2 = 0.f, g3 = 0.f;
#pragma unroll
        for (int mv = 0; mv < 6; mv++) {
            float4 kk = kp4[mv];
            g0 = fmaf(qp[4*mv  ], kk.x, g0);
            g1 = fmaf(qp[4*mv+1], kk.y, g1);
            g2 = fmaf(qp[4*mv+2], kk.z, g2);
            g3 = fmaf(qp[4*mv+3], kk.w, g3);
        }
        float g = (g0 + g1) + (g2 + g3);
        float w = (jg >= cstart) ? 0.875f : -0.125f;

        float coef = act ? (__expf(s - lse) + gps * w * g) : 0.f;

#pragma unroll
        for (int dv = 0; dv < 16; dv++) {
            float4 vv = __ldg(&vr4[dv]);
            o[4*dv  ] = fmaf(coef, vv.x, o[4*dv  ]);
            o[4*dv+1] = fmaf(coef, vv.y, o[4*dv+1]);
            o[4*dv+2] = fmaf(coef, vv.z, o[4*dv+2]);
            o[4*dv+3] = fmaf(coef, vv.w, o[4*dv+3]);
        }
    }

    // add gps * (q' . KVbase)
#pragma unroll
    for (int m = 0; m < Mc; m++) {
        float cm = gps * qp[m];
        const float4* kb4 = (const float4*)(kvb_s + m * Dc);
#pragma unroll
        for (int dv = 0; dv < 16; dv++) {
            float4 x = kb4[dv];
            o[4*dv  ] = fmaf(cm, x.x, o[4*dv  ]);
            o[4*dv+1] = fmaf(cm, x.y, o[4*dv+1]);
            o[4*dv+2] = fmaf(cm, x.z, o[4*dv+2]);
            o[4*dv+3] = fmaf(cm, x.w, o[4*dv+3]);
        }
    }

    float4* orow = (float4*)(out + ((size_t)i * Hc + h) * Dc);
#pragma unroll
    for (int dv = 0; dv < 16; dv++)
        orow[dv] = make_float4(o[4*dv], o[4*dv+1], o[4*dv+2], o[4*dv+3]);
}

// ---------------- launch ----------------------------------------------------
extern "C" void kernel_launch(void* const* d_in, const int* in_sizes, int n_in,
                              void* d_out, int out_size)
{
    (void)out_size;
    const float* qkv  = (const float*)d_in[0];
    const float* proj = (const float*)d_in[1];
    if (n_in >= 2 && in_sizes[0] < in_sizes[1]) {  // defensive order check
        const float* tmp = qkv; qkv = proj; proj = tmp;
    }
    float* out = (float*)d_out;

    cudaFuncSetAttribute(k4_main, cudaFuncAttributeMaxDynamicSharedMemorySize,
                         SM4_FLOATS * (int)sizeof(float));

    dim3 grid(NC, Hc);
    k1_feat  <<<grid, 128>>>(qkv, proj);
    k2_kprime<<<grid, 128>>>(qkv);
    k3_scan  <<<Hc, 256>>>();
    k4_main  <<<grid, 128, SM4_FLOATS * (int)sizeof(float)>>>(qkv, proj, out);
}